// round 6
// baseline (speedup 1.0000x reference)
#include <cuda_runtime.h>
#include <math.h>

// Inputs (metadata order):
// 0 rays_o[2,8192,3] f32   1 rays_d[2,8192,3] f32   2 uv_feat[2,65536,148] f32
// 3 transforms[16,3,4] f32 4 w0[211,256] f32        5 b0[256] f32
// 6 w1[256,256] f32        7 b1[256] f32            8 w_out[256,4] f32
// 9 b_out[4] f32          10 uv_idx[2,8192,64] i32 11 vox_idx[2,8192,64] i32
// out: rgb_map [2,8192,3] f32

struct Smem {
    float bufA[256 * 68];   // X (rows 0..210), later H2 (rows 0..255)
    float bufB[256 * 68];   // H1
    float Ts[16 * 12];
    float bs0[256];
    float bs1[256];
    float wouts[1024];
    float bouts[4];
    float raws[4][64];
    float alpha[64];
    float rgbs[3][64];
    float dn;
};

__device__ __forceinline__ unsigned long long fma2(unsigned long long a,
                                                   unsigned long long b,
                                                   unsigned long long c) {
    unsigned long long d;
    asm("fma.rn.f32x2 %0, %1, %2, %3;" : "=l"(d) : "l"(a), "l"(b), "l"(c));
    return d;
}
__device__ __forceinline__ unsigned long long dup2(float v) {
    unsigned long long r;
    asm("mov.b64 %0, {%1, %1};" : "=l"(r) : "f"(v));
    return r;
}
__device__ __forceinline__ void unpack2(unsigned long long u, float& a, float& b) {
    asm("mov.b64 {%0, %1}, %2;" : "=f"(a), "=f"(b) : "l"(u));
}

// Accurate sincos: fp32 Cody-Waite 2-term reduction (fma-exact) + MUFU core
// on |r| <= pi/4. Immune to --use_fast_math; good for |x| up to ~1e4.
__device__ __forceinline__ void sincos_acc(float x, float& s, float& c) {
    float q = rintf(x * 0.63661977236758134f);
    float r = fmaf(q, -1.5707962513e+00f, x);
    r = fmaf(q, -7.5497894159e-08f, r);
    int qi = (int)q & 3;
    float sr = __sinf(r), cr = __cosf(r);
    float ss = (qi & 1) ? cr : sr;
    float cc = (qi & 1) ? sr : cr;
    s = (qi & 2) ? -ss : ss;
    c = ((qi + 1) & 2) ? -cc : cc;
}

// H[n][m] = relu(sum_k Xs[k][m] * Wg[k*256+n] + bias[n]),  n in [0,256), m in [0,64)
// Thread tile: 4 n-rows x 4 m-cols; 4 chunks of 64 n-rows.
template <int K>
__device__ __forceinline__ void gemm(const float* __restrict__ Xs,
                                     const float* __restrict__ Wg,
                                     const float* __restrict__ bias,
                                     float* __restrict__ Hs, int tid) {
    const int mg = tid & 15;   // m-cols mg*4..mg*4+3
    const int ng = tid >> 4;   // n-rows (chunk-local) ng*4..ng*4+3
    const ulonglong2* X2 = (const ulonglong2*)Xs;   // [k][17 float4] view

#pragma unroll
    for (int c = 0; c < 4; ++c) {
        unsigned long long a01[4] = {0ull, 0ull, 0ull, 0ull};
        unsigned long long a23[4] = {0ull, 0ull, 0ull, 0ull};
        const float4* W4 = (const float4*)Wg + c * 16 + ng;   // row stride 64 float4

#pragma unroll 8
        for (int k = 0; k < K; ++k) {
            ulonglong2 xv = X2[k * 17 + mg];   // (x0,x1),(x2,x3)
            float4 wv = W4[k * 64];
            unsigned long long w;
            w = dup2(wv.x); a01[0] = fma2(xv.x, w, a01[0]); a23[0] = fma2(xv.y, w, a23[0]);
            w = dup2(wv.y); a01[1] = fma2(xv.x, w, a01[1]); a23[1] = fma2(xv.y, w, a23[1]);
            w = dup2(wv.z); a01[2] = fma2(xv.x, w, a01[2]); a23[2] = fma2(xv.y, w, a23[2]);
            w = dup2(wv.w); a01[3] = fma2(xv.x, w, a01[3]); a23[3] = fma2(xv.y, w, a23[3]);
        }

#pragma unroll
        for (int i = 0; i < 4; ++i) {
            int n = c * 64 + ng * 4 + i;
            float bv = bias[n];
            float f0, f1, f2, f3;
            unpack2(a01[i], f0, f1);
            unpack2(a23[i], f2, f3);
            float4 o;
            o.x = fmaxf(f0 + bv, 0.f);
            o.y = fmaxf(f1 + bv, 0.f);
            o.z = fmaxf(f2 + bv, 0.f);
            o.w = fmaxf(f3 + bv, 0.f);
            *(float4*)&Hs[n * 68 + mg * 4] = o;
        }
    }
}

__global__ __launch_bounds__(256, 1)
void vh_main(const float* __restrict__ rays_o, const float* __restrict__ rays_d,
             const float* __restrict__ uv_feat, const float* __restrict__ transforms,
             const float* __restrict__ w0, const float* __restrict__ b0,
             const float* __restrict__ w1, const float* __restrict__ b1,
             const float* __restrict__ w_out, const float* __restrict__ b_out,
             const int* __restrict__ uv_idx, const int* __restrict__ vox_idx,
             float* __restrict__ out) {
    extern __shared__ char sraw[];
    Smem* sm = (Smem*)sraw;
    const int tid = threadIdx.x;
    const int rid = blockIdx.x;          // b*8192 + r
    const int bb = rid >> 13;

    // stage constants
    if (tid < 192) sm->Ts[tid] = transforms[tid];
    sm->bs0[tid] = b0[tid];
    sm->bs1[tid] = b1[tid];
    for (int i = tid; i < 1024; i += 256) sm->wouts[i] = w_out[i];
    if (tid < 4) sm->bouts[tid] = b_out[tid];

    float ro0 = rays_o[rid * 3 + 0], ro1 = rays_o[rid * 3 + 1], ro2 = rays_o[rid * 3 + 2];
    float rd0 = rays_d[rid * 3 + 0], rd1 = rays_d[rid * 3 + 1], rd2 = rays_d[rid * 3 + 2];
    if (tid == 0) sm->dn = sqrtf(rd0 * rd0 + rd1 * rd1 + rd2 * rd2);
    __syncthreads();

    // ---- build X [211][64] in bufA (4 threads per point) ----
    {
        const int m = tid >> 2, j = tid & 3;
        const int p = rid * 64 + m;
        const int vox = vox_idx[p];
        const int uvi = uv_idx[p];
        float z = 0.5f + 0.0234375f * (float)m;   // NEAR + 1.5*m/64
        float px = fmaf(rd0, z, ro0);
        float py = fmaf(rd1, z, ro1);
        float pz = fmaf(rd2, z, ro2);
        const float* T = &sm->Ts[vox * 12];
        float cx = T[0] * px + T[1] * py + T[2]  * pz + T[3];
        float cy = T[4] * px + T[5] * py + T[6]  * pz + T[7];
        float cz = T[8] * px + T[9] * py + T[10] * pz + T[11];
        float* X = sm->bufA;
        if (j == 0) {
            X[0 * 68 + m] = cx;
            X[1 * 68 + m] = cy;
            X[2 * 68 + m] = cz;
        }
        for (int kf = j; kf < 10; kf += 4) {
            float f = (float)(1 << kf);
            float sx, cxs, sy, cys, sz, czs;
            sincos_acc(f * cx, sx, cxs);
            sincos_acc(f * cy, sy, cys);
            sincos_acc(f * cz, sz, czs);
            int row = 3 + 6 * kf;
            X[(row + 0) * 68 + m] = sx;
            X[(row + 1) * 68 + m] = sy;
            X[(row + 2) * 68 + m] = sz;
            X[(row + 3) * 68 + m] = cxs;
            X[(row + 4) * 68 + m] = cys;
            X[(row + 5) * 68 + m] = czs;
        }
        const float4* src =
            (const float4*)(uv_feat + ((long long)bb * 65536 + uvi) * 148);
        for (int f = j; f < 37; f += 4) {   // 148 floats = 37 float4
            float4 v = src[f];
            int row = 63 + f * 4;
            X[(row + 0) * 68 + m] = v.x;
            X[(row + 1) * 68 + m] = v.y;
            X[(row + 2) * 68 + m] = v.z;
            X[(row + 3) * 68 + m] = v.w;
        }
    }
    __syncthreads();

    // ---- MLP ----
    gemm<211>(sm->bufA, w0, sm->bs0, sm->bufB, tid);   // H1 = relu(X W0 + b0)
    __syncthreads();
    gemm<256>(sm->bufB, w1, sm->bs1, sm->bufA, tid);   // H2 = relu(H1 W1 + b1)
    __syncthreads();

    // ---- raw = H2^T w_out + b_out : thread = (m = tid>>2, c = tid&3) ----
    {
        const int c = tid & 3, m = tid >> 2;
        float acc = sm->bouts[c];
#pragma unroll 8
        for (int k = 0; k < 256; ++k)
            acc = fmaf(sm->bufA[k * 68 + m], sm->wouts[k * 4 + c], acc);
        sm->raws[c][m] = acc;
    }
    __syncthreads();

    // ---- sigmoid / relu / alpha ----
    if (tid < 64) {
        int m = tid;
        sm->rgbs[0][m] = 1.f / (1.f + __expf(-sm->raws[0][m]));
        sm->rgbs[1][m] = 1.f / (1.f + __expf(-sm->raws[1][m]));
        sm->rgbs[2][m] = 1.f / (1.f + __expf(-sm->raws[2][m]));
        float sig = fmaxf(sm->raws[3][m], 0.f);
        float dist = ((m == 63) ? 1e10f : 0.0234375f) * sm->dn;
        sm->alpha[m] = 1.f - __expf(-sig * dist);
    }
    __syncthreads();

    // ---- composite (sequential over 64 samples) ----
    if (tid == 0) {
        float t = 1.f, R = 0.f, G = 0.f, B = 0.f;
#pragma unroll
        for (int m = 0; m < 64; ++m) {
            float a = sm->alpha[m];
            float w = a * t;
            R = fmaf(w, sm->rgbs[0][m], R);
            G = fmaf(w, sm->rgbs[1][m], G);
            B = fmaf(w, sm->rgbs[2][m], B);
            t = t * (1.f - a + 1e-10f);
        }
        out[rid * 3 + 0] = R;
        out[rid * 3 + 1] = G;
        out[rid * 3 + 2] = B;
    }
}

extern "C" void kernel_launch(void* const* d_in, const int* in_sizes, int n_in,
                              void* d_out, int out_size) {
    const float* rays_o     = (const float*)d_in[0];
    const float* rays_d     = (const float*)d_in[1];
    const float* uv_feat    = (const float*)d_in[2];
    const float* transforms = (const float*)d_in[3];
    const float* w0         = (const float*)d_in[4];
    const float* b0         = (const float*)d_in[5];
    const float* w1         = (const float*)d_in[6];
    const float* b1         = (const float*)d_in[7];
    const float* w_out      = (const float*)d_in[8];
    const float* b_out      = (const float*)d_in[9];
    const int*   uv_idx     = (const int*)d_in[10];
    const int*   vox_idx    = (const int*)d_in[11];
    float* out = (float*)d_out;

    cudaFuncSetAttribute(vh_main, cudaFuncAttributeMaxDynamicSharedMemorySize,
                         (int)sizeof(Smem));
    vh_main<<<16384, 256, sizeof(Smem)>>>(
        rays_o, rays_d, uv_feat, transforms, w0, b0, w1, b1, w_out, b_out,
        uv_idx, vox_idx, out);
}

// round 10
// speedup vs baseline: 2.4492x; 2.4492x over previous
#include <cuda_runtime.h>
#include <cuda_fp16.h>
#include <math.h>
#include <stdint.h>

// ---------------------------------------------------------------------------
// VoxelHuman fused NeRF renderer — split-fp16 (hi+lo) mma.sync, fp32 accum.
// Per CTA: 2 rays -> M=128 points. MLP 224(K-pad)->256 and 256->256 on tensor
// cores with 3-pass error compensation; output layer + compositing in fp32.
//
// smem unit: uint2 {half2 hi, half2 lo} per (row, k-pair). Same 8 bytes/k-pair
// as the old float2 layout -> identical smem budget and streaming bytes.
// Input column permutation: cols 0..147 = uv features, 148..210 = pos embed,
// 211..223 = zero pad (prep kernel permutes W0 rows to match).
// ---------------------------------------------------------------------------

#define NCH1 7                 // layer-1 chunks (28 ksteps, K pad 211->224)
#define NCH2 8                 // layer-2 chunks (32 ksteps, K=256)
#define NCHT 15
#define CHUNK_U2 4096          // 4 ksteps * 256 n * 4 q  (uint2 units)
#define CHUNK_BYTES 32768

__device__ uint2 g_wt1[NCH1 * CHUNK_U2];   // split-fp16 W0 (permuted rows)
__device__ uint2 g_wt2[NCH2 * CHUNK_U2];   // split-fp16 W1

// smem offsets (bytes)
#define OFF_ACT   0            // 131072 (32 ksteps x 128 rows x 4 q x 8B)
#define OFF_WBUF  131072       // 2 x 32768
#define OFF_PRAW  196608       // 128*4*4 floats = 8192
#define OFF_WOUT  204800       // 1024 floats
#define OFF_B0    208896       // 256
#define OFF_B1    209920       // 256
#define OFF_TS    210944       // 192
#define OFF_BOUT  211712       // 4
#define OFF_DNS   211728       // 2
#define OFF_ALPH  211744       // 128
#define OFF_RGB   212256       // 384
#define OFF_MBAR  213792       // 2 x u64
#define DYN_SMEM  213824

__device__ __forceinline__ uint32_t h2u(half2 h) {
    uint32_t u; asm("mov.b32 %0, %1;" : "=r"(u) : "r"(*(uint32_t*)&h)); return u;
}
__device__ __forceinline__ uint2 split2(float x0, float x1) {
    half2 h = __floats2half2_rn(x0, x1);
    float2 hf = __half22float2(h);
    half2 l = __floats2half2_rn(x0 - hf.x, x1 - hf.y);
    uint2 r;
    r.x = *(uint32_t*)&h;
    r.y = *(uint32_t*)&l;
    return r;
}
__device__ __forceinline__ uint32_t smem_u32(const void* p) {
    return (uint32_t)__cvta_generic_to_shared(p);
}
__device__ __forceinline__ void mbar_init(uint32_t mb, uint32_t cnt) {
    asm volatile("mbarrier.init.shared.b64 [%0], %1;" :: "r"(mb), "r"(cnt) : "memory");
}
__device__ __forceinline__ void mbar_wait(uint32_t mb, int parity) {
    asm volatile(
        "{\n\t.reg .pred P;\n"
        "W_%=:\n\t"
        "mbarrier.try_wait.parity.acquire.cta.shared::cta.b64 P, [%0], %1, 0x989680;\n\t"
        "@!P bra W_%=;\n\t}"
        :: "r"(mb), "r"(parity) : "memory");
}
__device__ __forceinline__ void fence_proxy_async() {
    asm volatile("fence.proxy.async.shared::cta;" ::: "memory");
}
__device__ __forceinline__ void issue_chunk(int c, uint32_t dst, uint32_t mb) {
    const uint2* src = (c < NCH1) ? (g_wt1 + c * CHUNK_U2)
                                  : (g_wt2 + (c - NCH1) * CHUNK_U2);
    asm volatile("mbarrier.arrive.expect_tx.shared.b64 _, [%0], %1;"
                 :: "r"(mb), "r"((uint32_t)CHUNK_BYTES) : "memory");
    asm volatile(
        "cp.async.bulk.shared::cluster.global.mbarrier::complete_tx::bytes "
        "[%0], [%1], %2, [%3];"
        :: "r"(dst), "l"(src), "r"((uint32_t)CHUNK_BYTES), "r"(mb) : "memory");
}

// m16n8k8 fp16 mma, fp32 accum: D += A*B. a0 = row g k-pair, a1 = row g+8.
__device__ __forceinline__ void mma_h(float d[4], uint32_t a0, uint32_t a1,
                                      uint32_t b0) {
    asm volatile(
        "mma.sync.aligned.m16n8k8.row.col.f32.f16.f16.f32 "
        "{%0,%1,%2,%3}, {%4,%5}, {%6}, {%0,%1,%2,%3};"
        : "+f"(d[0]), "+f"(d[1]), "+f"(d[2]), "+f"(d[3])
        : "r"(a0), "r"(a1), "r"(b0));
}

// Accurate sincos (immune to --use_fast_math): fp32 Cody-Waite + MUFU.
__device__ __forceinline__ void sincos_acc(float x, float& s, float& c) {
    float q = rintf(x * 0.63661977236758134f);
    float r = fmaf(q, -1.5707962513e+00f, x);
    r = fmaf(q, -7.5497894159e-08f, r);
    int qi = (int)q & 3;
    float sr = __sinf(r), cr = __cosf(r);
    float ss = (qi & 1) ? cr : sr;
    float cc = (qi & 1) ? sr : cr;
    s = (qi & 2) ? -ss : ss;
    c = ((qi + 1) & 2) ? -cc : cc;
}

// ---------------------------------------------------------------------------
// Prep: transpose + fp16-split weights into paired fragment layout.
// uint2 index i: s = i>>10 (kstep), n = (i>>2)&255, q = i&3; k-pair 8s+2q,+1.
// Layer-1 K-col -> W0 row permutation: col<148 -> 63+col (features);
// col in [148,211) -> col-148 (embedding); col>=211 -> zero pad.
// ---------------------------------------------------------------------------
__global__ void vh_prep(const float* __restrict__ w0, const float* __restrict__ w1) {
    int i = blockIdx.x * 256 + threadIdx.x;   // 32768 threads
    int s = i >> 10, n = (i >> 2) & 255, q = i & 3;
    int k0 = 8 * s + 2 * q, k1 = k0 + 1;
    if (s < NCH1 * 4) {
        int r0 = (k0 < 148) ? 63 + k0 : ((k0 < 211) ? k0 - 148 : -1);
        int r1 = (k1 < 148) ? 63 + k1 : ((k1 < 211) ? k1 - 148 : -1);
        float v0 = (r0 >= 0) ? w0[r0 * 256 + n] : 0.f;
        float v1 = (r1 >= 0) ? w0[r1 * 256 + n] : 0.f;
        g_wt1[i] = split2(v0, v1);
    }
    g_wt2[i] = split2(w1[k0 * 256 + n], w1[k1 * 256 + n]);
}

// one k-step: load A frags (4 m-tiles) + B frags (8 n-frags), 96 mma (3-pass)
__device__ __forceinline__ void do_kstep(const uint2* __restrict__ A2,
                                         const uint2* __restrict__ wc,
                                         int s, int ks, int rbase, int nbase,
                                         int q, float acc[4][8][4]) {
    uint2 al[4], ah[4], bf[8];
#pragma unroll
    for (int mt = 0; mt < 4; ++mt) {
        int m = rbase + mt * 16;
        al[mt] = A2[(s * 128 + m) * 4 + q];
        ah[mt] = A2[(s * 128 + m + 8) * 4 + q];
    }
#pragma unroll
    for (int j = 0; j < 8; ++j) {
        int n = nbase + j * 8;
        bf[j] = wc[(ks * 256 + n) * 4 + q];
    }
#pragma unroll
    for (int mt = 0; mt < 4; ++mt)
#pragma unroll
        for (int j = 0; j < 8; ++j) {
            mma_h(acc[mt][j], al[mt].x, ah[mt].x, bf[j].x);   // hi*hi
            mma_h(acc[mt][j], al[mt].x, ah[mt].x, bf[j].y);   // hi*lo
            mma_h(acc[mt][j], al[mt].y, ah[mt].y, bf[j].x);   // lo*hi
        }
}

__global__ __launch_bounds__(256, 1)
void vh_tc(const float* __restrict__ rays_o, const float* __restrict__ rays_d,
           const float* __restrict__ uv_feat, const float* __restrict__ transforms,
           const float* __restrict__ b0, const float* __restrict__ b1,
           const float* __restrict__ w_out, const float* __restrict__ b_out,
           const int* __restrict__ uv_idx, const int* __restrict__ vox_idx,
           float* __restrict__ out) {
    extern __shared__ char dsm[];
    const int tid = threadIdx.x;
    const int wid = tid >> 5, lane = tid & 31;
    const int g = lane >> 2, q = lane & 3;
    const int warp_m = wid & 1, warp_n = wid >> 1;   // 2 x 4 warp grid

    uint2* act   = (uint2*)(dsm + OFF_ACT);
    float* praw  = (float*)(dsm + OFF_PRAW);
    float* wouts = (float*)(dsm + OFF_WOUT);
    float* b0s   = (float*)(dsm + OFF_B0);
    float* b1s   = (float*)(dsm + OFF_B1);
    float* Ts    = (float*)(dsm + OFF_TS);
    float* bouts = (float*)(dsm + OFF_BOUT);
    float* dns   = (float*)(dsm + OFF_DNS);
    float* alphas = (float*)(dsm + OFF_ALPH);
    float* rgbsm  = (float*)(dsm + OFF_RGB);
    uint32_t mbf[2] = {smem_u32(dsm + OFF_MBAR), smem_u32(dsm + OFF_MBAR + 8)};
    uint32_t wdst[2] = {smem_u32(dsm + OFF_WBUF), smem_u32(dsm + OFF_WBUF + CHUNK_BYTES)};

    // kick off weight streaming immediately (overlaps with build phase)
    if (tid == 0) {
        mbar_init(mbf[0], 1);
        mbar_init(mbf[1], 1);
        fence_proxy_async();
        issue_chunk(0, wdst[0], mbf[0]);
        issue_chunk(1, wdst[1], mbf[1]);
    }

    // stage constants
    if (tid < 192) Ts[tid] = transforms[tid];
    b0s[tid] = b0[tid];
    b1s[tid] = b1[tid];
    for (int i = tid; i < 1024; i += 256) wouts[i] = w_out[i];
    if (tid < 4) bouts[tid] = b_out[tid];
    __syncthreads();

    // ---- build X [128 rows][224 cols] as split-fp16 pairs (2 threads / row) ----
    {
        const int m = tid >> 1, j = tid & 1;
        const int rid = blockIdx.x * 2 + (m >> 6);
        const int samp = m & 63;
        // uint2 slot for (m, even col c): ((c>>3)*128 + m)*4 + ((c>>1)&3)
        if (j == 0) {
            // embedding -> cols 148..210, pad 211..223
            float ro0 = rays_o[rid * 3], ro1 = rays_o[rid * 3 + 1], ro2 = rays_o[rid * 3 + 2];
            float rd0 = rays_d[rid * 3], rd1 = rays_d[rid * 3 + 1], rd2 = rays_d[rid * 3 + 2];
            if (samp == 0)
                dns[m >> 6] = sqrtf(rd0 * rd0 + rd1 * rd1 + rd2 * rd2);
            int vox = vox_idx[rid * 64 + samp];
            float z = 0.5f + 0.0234375f * (float)samp;
            float px = fmaf(rd0, z, ro0), py = fmaf(rd1, z, ro1), pz = fmaf(rd2, z, ro2);
            const float* T = &Ts[vox * 12];
            float cx = T[0] * px + T[1] * py + T[2]  * pz + T[3];
            float cy = T[4] * px + T[5] * py + T[6]  * pz + T[7];
            float cz = T[8] * px + T[9] * py + T[10] * pz + T[11];
            float e[64];
            e[0] = cx; e[1] = cy; e[2] = cz; e[63] = 0.f;
#pragma unroll
            for (int kf = 0; kf < 10; ++kf) {
                float f = (float)(1 << kf);
                float sx, cxs, sy, cys, sz, czs;
                sincos_acc(f * cx, sx, cxs);
                sincos_acc(f * cy, sy, cys);
                sincos_acc(f * cz, sz, czs);
                int r = 3 + 6 * kf;
                e[r + 0] = sx; e[r + 1] = sy; e[r + 2] = sz;
                e[r + 3] = cxs; e[r + 4] = cys; e[r + 5] = czs;
            }
#pragma unroll
            for (int pe = 0; pe < 32; ++pe) {
                int c = 148 + 2 * pe;
                act[((c >> 3) * 128 + m) * 4 + ((c >> 1) & 3)] = split2(e[2 * pe], e[2 * pe + 1]);
            }
            uint2 zz; zz.x = 0u; zz.y = 0u;
#pragma unroll
            for (int pc = 0; pc < 6; ++pc) {
                int c = 212 + 2 * pc;
                act[((c >> 3) * 128 + m) * 4 + ((c >> 1) & 3)] = zz;
            }
        } else {
            // features -> cols 0..147 (pair- and float4-aligned)
            int uvi = uv_idx[rid * 64 + samp];
            const float4* src =
                (const float4*)(uv_feat + ((long long)(rid >> 13) * 65536 + uvi) * 148);
#pragma unroll 4
            for (int f = 0; f < 37; ++f) {
                float4 v = src[f];
                int c0 = 4 * f, c1 = 4 * f + 2;
                act[((c0 >> 3) * 128 + m) * 4 + ((c0 >> 1) & 3)] = split2(v.x, v.y);
                act[((c1 >> 3) * 128 + m) * 4 + ((c1 >> 1) & 3)] = split2(v.z, v.w);
            }
        }
    }
    __syncthreads();

    const int rbase = warp_m * 64 + g;
    const int nbase = warp_n * 64 + g;
    int ph[2] = {0, 0};
    float acc[4][8][4];

    // ---- layer 1: D1 = X @ W0 (7 chunks) ----
#pragma unroll
    for (int mt = 0; mt < 4; ++mt)
#pragma unroll
        for (int j = 0; j < 8; ++j)
#pragma unroll
            for (int i = 0; i < 4; ++i) acc[mt][j][i] = 0.f;

    for (int c = 0; c < NCH1; ++c) {
        int b = c & 1;
        mbar_wait(mbf[b], ph[b]); ph[b] ^= 1;
        const uint2* wc = (const uint2*)(dsm + OFF_WBUF + b * CHUNK_BYTES);
#pragma unroll
        for (int ks = 0; ks < 4; ++ks)
            do_kstep(act, wc, c * 4 + ks, ks, rbase, nbase, q, acc);
        __syncthreads();
        if (tid == 0 && c + 2 < NCHT) {
            fence_proxy_async();
            issue_chunk(c + 2, wdst[b], mbf[b]);
        }
    }

    // ---- epilogue 1: Act <- split(relu(D1 + b0)) (overwrites union; synced) ----
#pragma unroll
    for (int mt = 0; mt < 4; ++mt)
#pragma unroll
        for (int j = 0; j < 8; ++j) {
            int n = warp_n * 64 + j * 8 + 2 * q;
            float2 bp = *(const float2*)&b0s[n];
            int m = warp_m * 64 + mt * 16 + g;
            int sidx = warp_n * 8 + j;
            float h0 = fmaxf(acc[mt][j][0] + bp.x, 0.f);
            float h1 = fmaxf(acc[mt][j][1] + bp.y, 0.f);
            float h2 = fmaxf(acc[mt][j][2] + bp.x, 0.f);
            float h3 = fmaxf(acc[mt][j][3] + bp.y, 0.f);
            act[(sidx * 128 + m) * 4 + q] = split2(h0, h1);
            act[(sidx * 128 + m + 8) * 4 + q] = split2(h2, h3);
        }
    __syncthreads();

    // ---- layer 2: D2 = H1 @ W1 (8 chunks) ----
#pragma unroll
    for (int mt = 0; mt < 4; ++mt)
#pragma unroll
        for (int j = 0; j < 8; ++j)
#pragma unroll
            for (int i = 0; i < 4; ++i) acc[mt][j][i] = 0.f;

    for (int c = NCH1; c < NCHT; ++c) {
        int b = c & 1;
        mbar_wait(mbf[b], ph[b]); ph[b] ^= 1;
        const uint2* wc = (const uint2*)(dsm + OFF_WBUF + b * CHUNK_BYTES);
#pragma unroll
        for (int ks = 0; ks < 4; ++ks)
            do_kstep(act, wc, (c - NCH1) * 4 + ks, ks, rbase, nbase, q, acc);
        __syncthreads();
        if (tid == 0 && c + 2 < NCHT) {
            fence_proxy_async();
            issue_chunk(c + 2, wdst[b], mbf[b]);
        }
    }

    // ---- output layer: per-warp partial dots + quad reduce ----
    {
        float po[8][4];
#pragma unroll
        for (int r8 = 0; r8 < 8; ++r8)
#pragma unroll
            for (int o = 0; o < 4; ++o) po[r8][o] = 0.f;

#pragma unroll
        for (int mt = 0; mt < 4; ++mt)
#pragma unroll
            for (int j = 0; j < 8; ++j) {
                int n = warp_n * 64 + j * 8 + 2 * q;
                float2 bp = *(const float2*)&b1s[n];
                float4 wa = *(const float4*)&wouts[n * 4];
                float4 wb = *(const float4*)&wouts[(n + 1) * 4];
                float h0 = fmaxf(acc[mt][j][0] + bp.x, 0.f);
                float h1 = fmaxf(acc[mt][j][1] + bp.y, 0.f);
                float h2 = fmaxf(acc[mt][j][2] + bp.x, 0.f);
                float h3 = fmaxf(acc[mt][j][3] + bp.y, 0.f);
                po[mt * 2 + 0][0] += h0 * wa.x + h1 * wb.x;
                po[mt * 2 + 0][1] += h0 * wa.y + h1 * wb.y;
                po[mt * 2 + 0][2] += h0 * wa.z + h1 * wb.z;
                po[mt * 2 + 0][3] += h0 * wa.w + h1 * wb.w;
                po[mt * 2 + 1][0] += h2 * wa.x + h3 * wb.x;
                po[mt * 2 + 1][1] += h2 * wa.y + h3 * wb.y;
                po[mt * 2 + 1][2] += h2 * wa.z + h3 * wb.z;
                po[mt * 2 + 1][3] += h2 * wa.w + h3 * wb.w;
            }
#pragma unroll
        for (int r8 = 0; r8 < 8; ++r8)
#pragma unroll
            for (int o = 0; o < 4; ++o) {
                float v = po[r8][o];
                v += __shfl_xor_sync(0xFFFFFFFFu, v, 1);
                v += __shfl_xor_sync(0xFFFFFFFFu, v, 2);
                po[r8][o] = v;
            }
        if (q == 0) {
#pragma unroll
            for (int r8 = 0; r8 < 8; ++r8) {
                int m = warp_m * 64 + (r8 >> 1) * 16 + g + (r8 & 1) * 8;
#pragma unroll
                for (int o = 0; o < 4; ++o)
                    praw[(m * 4 + o) * 4 + warp_n] = po[r8][o];
            }
        }
    }
    __syncthreads();

    // ---- shading ----
    if (tid < 128) {
        int m = tid, samp = m & 63;
        float raw[4];
#pragma unroll
        for (int o = 0; o < 4; ++o) {
            const float* p = &praw[(m * 4 + o) * 4];
            raw[o] = bouts[o] + p[0] + p[1] + p[2] + p[3];
        }
        rgbsm[0 * 128 + m] = 1.f / (1.f + __expf(-raw[0]));
        rgbsm[1 * 128 + m] = 1.f / (1.f + __expf(-raw[1]));
        rgbsm[2 * 128 + m] = 1.f / (1.f + __expf(-raw[2]));
        float sig = fmaxf(raw[3], 0.f);
        float dist = ((samp == 63) ? 1e10f : 0.0234375f) * dns[m >> 6];
        alphas[m] = 1.f - __expf(-sig * dist);
    }
    __syncthreads();

    // ---- composite ----
    if (tid < 2) {
        float t = 1.f, R = 0.f, G = 0.f, B = 0.f;
        int base = tid * 64;
#pragma unroll
        for (int s = 0; s < 64; ++s) {
            float a = alphas[base + s];
            float w = a * t;
            R = fmaf(w, rgbsm[0 * 128 + base + s], R);
            G = fmaf(w, rgbsm[1 * 128 + base + s], G);
            B = fmaf(w, rgbsm[2 * 128 + base + s], B);
            t = t * (1.f - a + 1e-10f);
        }
        int rid = blockIdx.x * 2 + tid;
        out[rid * 3 + 0] = R;
        out[rid * 3 + 1] = G;
        out[rid * 3 + 2] = B;
    }
}

extern "C" void kernel_launch(void* const* d_in, const int* in_sizes, int n_in,
                              void* d_out, int out_size) {
    const float* rays_o     = (const float*)d_in[0];
    const float* rays_d     = (const float*)d_in[1];
    const float* uv_feat    = (const float*)d_in[2];
    const float* transforms = (const float*)d_in[3];
    const float* w0         = (const float*)d_in[4];
    const float* b0         = (const float*)d_in[5];
    const float* w1         = (const float*)d_in[6];
    const float* b1         = (const float*)d_in[7];
    const float* w_out      = (const float*)d_in[8];
    const float* b_out      = (const float*)d_in[9];
    const int*   uv_idx     = (const int*)d_in[10];
    const int*   vox_idx    = (const int*)d_in[11];
    float* out = (float*)d_out;

    vh_prep<<<128, 256>>>(w0, w1);

    cudaFuncSetAttribute(vh_tc, cudaFuncAttributeMaxDynamicSharedMemorySize, DYN_SMEM);
    vh_tc<<<8192, 256, DYN_SMEM>>>(rays_o, rays_d, uv_feat, transforms,
                                   b0, b1, w_out, b_out, uv_idx, vox_idx, out);
}

// round 12
// speedup vs baseline: 2.9341x; 1.1980x over previous
#include <cuda_runtime.h>
#include <cuda_fp16.h>
#include <math.h>
#include <stdint.h>

// ---------------------------------------------------------------------------
// VoxelHuman fused NeRF renderer — split-fp16 (hi+lo) mma.sync m16n8k16,
// fp32 accum, 3-pass error compensation. 2 CTAs/SM (M=64, 1 ray per CTA)
// so scalar phases of one CTA overlap MMA phases of the other.
// ---------------------------------------------------------------------------

#define NCH1 14                // layer-1 chunks (2 ksteps each; K pad 211->224)
#define NCH2 16                // layer-2 chunks (K = 256)
#define NCHT 30
#define CHUNK_U2 2048          // 2 ksteps * 256 n * 4 q (uint2 units)
#define CHUNK_BYTES 16384

__device__ uint2 g_wt1[28 * 1024];   // split-fp16 W0 (permuted rows), kstep-major
__device__ uint2 g_wt2[32 * 1024];   // split-fp16 W1

// smem offsets (bytes), per CTA
#define OFF_ACT   0            // 65536 (32 ksteps x 64 rows x 4 q x 8B)
#define OFF_WBUF  65536        // 2 x 16384
#define OFF_PRAW  98304        // 64*4*8 floats = 8192
#define OFF_WOUT  106496       // 1024 floats
#define OFF_B0    110592       // 256 floats
#define OFF_B1    111616       // 256 floats
#define OFF_TS    112640       // 192 floats
#define OFF_BOUT  113408       // 4 floats
#define OFF_DNS   113424       // 1 float
#define OFF_ALPH  113440       // 64 floats
#define OFF_RGB   113696       // 192 floats
#define OFF_MBAR  114464       // 2 x u64
#define DYN_SMEM  114688

__device__ __forceinline__ uint2 split2(float x0, float x1) {
    half2 h = __floats2half2_rn(x0, x1);
    float2 hf = __half22float2(h);
    half2 l = __floats2half2_rn(x0 - hf.x, x1 - hf.y);
    uint2 r;
    r.x = *(uint32_t*)&h;
    r.y = *(uint32_t*)&l;
    return r;
}
__device__ __forceinline__ uint32_t smem_u32(const void* p) {
    return (uint32_t)__cvta_generic_to_shared(p);
}
__device__ __forceinline__ void mbar_init(uint32_t mb, uint32_t cnt) {
    asm volatile("mbarrier.init.shared.b64 [%0], %1;" :: "r"(mb), "r"(cnt) : "memory");
}
__device__ __forceinline__ void mbar_wait(uint32_t mb, int parity) {
    asm volatile(
        "{\n\t.reg .pred P;\n"
        "W_%=:\n\t"
        "mbarrier.try_wait.parity.acquire.cta.shared::cta.b64 P, [%0], %1, 0x989680;\n\t"
        "@!P bra W_%=;\n\t}"
        :: "r"(mb), "r"(parity) : "memory");
}
__device__ __forceinline__ void fence_proxy_async() {
    asm volatile("fence.proxy.async.shared::cta;" ::: "memory");
}
__device__ __forceinline__ void issue_chunk(int c, uint32_t dst, uint32_t mb) {
    const uint2* src = (c < NCH1) ? (g_wt1 + c * CHUNK_U2)
                                  : (g_wt2 + (c - NCH1) * CHUNK_U2);
    asm volatile("mbarrier.arrive.expect_tx.shared.b64 _, [%0], %1;"
                 :: "r"(mb), "r"((uint32_t)CHUNK_BYTES) : "memory");
    asm volatile(
        "cp.async.bulk.shared::cluster.global.mbarrier::complete_tx::bytes "
        "[%0], [%1], %2, [%3];"
        :: "r"(dst), "l"(src), "r"((uint32_t)CHUNK_BYTES), "r"(mb) : "memory");
}

// m16n8k16 fp16 mma, fp32 accum: D += A*B.
// a0=(row g, k0..1) a1=(row g+8, k0..1) a2=(row g, k8..9) a3=(row g+8, k8..9)
// b0=(k0..1, col g) b1=(k8..9, col g)  [k-pair index = 2q within each k8 half]
__device__ __forceinline__ void mma16(float d[4], uint32_t a0, uint32_t a1,
                                      uint32_t a2, uint32_t a3,
                                      uint32_t b0, uint32_t b1) {
    asm volatile(
        "mma.sync.aligned.m16n8k16.row.col.f32.f16.f16.f32 "
        "{%0,%1,%2,%3}, {%4,%5,%6,%7}, {%8,%9}, {%0,%1,%2,%3};"
        : "+f"(d[0]), "+f"(d[1]), "+f"(d[2]), "+f"(d[3])
        : "r"(a0), "r"(a1), "r"(a2), "r"(a3), "r"(b0), "r"(b1));
}

// Accurate sincos (immune to --use_fast_math): fp32 Cody-Waite + MUFU.
__device__ __forceinline__ void sincos_acc(float x, float& s, float& c) {
    float q = rintf(x * 0.63661977236758134f);
    float r = fmaf(q, -1.5707962513e+00f, x);
    r = fmaf(q, -7.5497894159e-08f, r);
    int qi = (int)q & 3;
    float sr = __sinf(r), cr = __cosf(r);
    float ss = (qi & 1) ? cr : sr;
    float cc = (qi & 1) ? sr : cr;
    s = (qi & 2) ? -ss : ss;
    c = ((qi + 1) & 2) ? -cc : cc;
}

// ---------------------------------------------------------------------------
// Prep: transpose + fp16-split weights into paired fragment layout.
// uint2 index i: s = i>>10 (kstep), n = (i>>2)&255, q = i&3; k-pair 8s+2q,+1.
// Layer-1 K-col -> W0 row permutation: col<148 -> 63+col (features);
// col in [148,211) -> col-148 (embedding); col>=211 -> zero pad.
// ---------------------------------------------------------------------------
__global__ void vh_prep(const float* __restrict__ w0, const float* __restrict__ w1) {
    int i = blockIdx.x * 256 + threadIdx.x;   // 32768 threads
    int s = i >> 10, n = (i >> 2) & 255, q = i & 3;
    int k0 = 8 * s + 2 * q, k1 = k0 + 1;
    if (s < 28) {
        int r0 = (k0 < 148) ? 63 + k0 : ((k0 < 211) ? k0 - 148 : -1);
        int r1 = (k1 < 148) ? 63 + k1 : ((k1 < 211) ? k1 - 148 : -1);
        float v0 = (r0 >= 0) ? w0[r0 * 256 + n] : 0.f;
        float v1 = (r1 >= 0) ? w0[r1 * 256 + n] : 0.f;
        g_wt1[i] = split2(v0, v1);
    }
    g_wt2[i] = split2(w1[k0 * 256 + n], w1[k1 * 256 + n]);
}

// one chunk = one k16 step. Warp w owns cols [32w, 32w+32). 48 mma (3-pass).
__device__ __forceinline__ void do_chunk(const uint2* __restrict__ act,
                                         const uint2* __restrict__ wc,
                                         int s0, int g, int q, int w,
                                         float acc[4][4][4]) {
    uint2 b0[4], b1[4];
#pragma unroll
    for (int j = 0; j < 4; ++j) {
        int n = w * 32 + j * 8 + g;
        b0[j] = wc[n * 4 + q];
        b1[j] = wc[(256 + n) * 4 + q];
    }
#pragma unroll
    for (int mt = 0; mt < 4; ++mt) {
        int m = mt * 16 + g;
        uint2 a00 = act[(s0 * 64 + m) * 4 + q];
        uint2 a01 = act[(s0 * 64 + m + 8) * 4 + q];
        uint2 a10 = act[((s0 + 1) * 64 + m) * 4 + q];
        uint2 a11 = act[((s0 + 1) * 64 + m + 8) * 4 + q];
#pragma unroll
        for (int j = 0; j < 4; ++j) {
            mma16(acc[mt][j], a00.x, a01.x, a10.x, a11.x, b0[j].x, b1[j].x); // hi*hi
            mma16(acc[mt][j], a00.x, a01.x, a10.x, a11.x, b0[j].y, b1[j].y); // hi*lo
            mma16(acc[mt][j], a00.y, a01.y, a10.y, a11.y, b0[j].x, b1[j].x); // lo*hi
        }
    }
}

__global__ __launch_bounds__(256, 2)
void vh_tc(const float* __restrict__ rays_o, const float* __restrict__ rays_d,
           const float* __restrict__ uv_feat, const float* __restrict__ transforms,
           const float* __restrict__ b0, const float* __restrict__ b1,
           const float* __restrict__ w_out, const float* __restrict__ b_out,
           const int* __restrict__ uv_idx, const int* __restrict__ vox_idx,
           float* __restrict__ out) {
    extern __shared__ char dsm[];
    const int tid = threadIdx.x;
    const int wid = tid >> 5, lane = tid & 31;
    const int g = lane >> 2, q = lane & 3;
    const int rid = blockIdx.x;                  // 1 ray per CTA

    uint2* act   = (uint2*)(dsm + OFF_ACT);
    float* praw  = (float*)(dsm + OFF_PRAW);
    float* wouts = (float*)(dsm + OFF_WOUT);
    float* b0s   = (float*)(dsm + OFF_B0);
    float* b1s   = (float*)(dsm + OFF_B1);
    float* Ts    = (float*)(dsm + OFF_TS);
    float* bouts = (float*)(dsm + OFF_BOUT);
    float* dns   = (float*)(dsm + OFF_DNS);
    float* alphas = (float*)(dsm + OFF_ALPH);
    float* rgbsm  = (float*)(dsm + OFF_RGB);
    uint32_t mbf[2] = {smem_u32(dsm + OFF_MBAR), smem_u32(dsm + OFF_MBAR + 8)};
    uint32_t wdst[2] = {smem_u32(dsm + OFF_WBUF), smem_u32(dsm + OFF_WBUF + CHUNK_BYTES)};

    // kick off weight streaming immediately (overlaps with build phase)
    if (tid == 0) {
        mbar_init(mbf[0], 1);
        mbar_init(mbf[1], 1);
        fence_proxy_async();
        issue_chunk(0, wdst[0], mbf[0]);
        issue_chunk(1, wdst[1], mbf[1]);
    }

    // stage constants
    if (tid < 192) Ts[tid] = transforms[tid];
    b0s[tid] = b0[tid];
    b1s[tid] = b1[tid];
    for (int i = tid; i < 1024; i += 256) wouts[i] = w_out[i];
    if (tid < 4) bouts[tid] = b_out[tid];
    __syncthreads();

    // ---- build X [64 rows][224 cols] as split-fp16 pairs (4 threads / row) ----
    {
        const int m = tid >> 2, j = tid & 3;   // m = sample
        // uint2 slot for (m, even col c): ((c>>3)*64 + m)*4 + ((c>>1)&3)
        if (j == 0) {
            // embedding -> cols 148..210, pad 211..223
            float ro0 = rays_o[rid * 3], ro1 = rays_o[rid * 3 + 1], ro2 = rays_o[rid * 3 + 2];
            float rd0 = rays_d[rid * 3], rd1 = rays_d[rid * 3 + 1], rd2 = rays_d[rid * 3 + 2];
            if (m == 0)
                dns[0] = sqrtf(rd0 * rd0 + rd1 * rd1 + rd2 * rd2);
            int vox = vox_idx[rid * 64 + m];
            float z = 0.5f + 0.0234375f * (float)m;
            float px = fmaf(rd0, z, ro0), py = fmaf(rd1, z, ro1), pz = fmaf(rd2, z, ro2);
            const float* T = &Ts[vox * 12];
            float cx = T[0] * px + T[1] * py + T[2]  * pz + T[3];
            float cy = T[4] * px + T[5] * py + T[6]  * pz + T[7];
            float cz = T[8] * px + T[9] * py + T[10] * pz + T[11];
            float e[64];
            e[0] = cx; e[1] = cy; e[2] = cz; e[63] = 0.f;
#pragma unroll
            for (int kf = 0; kf < 10; ++kf) {
                float f = (float)(1 << kf);
                float sx, cxs, sy, cys, sz, czs;
                sincos_acc(f * cx, sx, cxs);
                sincos_acc(f * cy, sy, cys);
                sincos_acc(f * cz, sz, czs);
                int r = 3 + 6 * kf;
                e[r + 0] = sx; e[r + 1] = sy; e[r + 2] = sz;
                e[r + 3] = cxs; e[r + 4] = cys; e[r + 5] = czs;
            }
#pragma unroll
            for (int pe = 0; pe < 32; ++pe) {
                int c = 148 + 2 * pe;
                act[((c >> 3) * 64 + m) * 4 + ((c >> 1) & 3)] = split2(e[2 * pe], e[2 * pe + 1]);
            }
            uint2 zz; zz.x = 0u; zz.y = 0u;
#pragma unroll
            for (int pc = 0; pc < 6; ++pc) {
                int c = 212 + 2 * pc;
                act[((c >> 3) * 64 + m) * 4 + ((c >> 1) & 3)] = zz;
            }
        } else {
            // features -> cols 0..147 (j=1,2,3 split the 37 float4s)
            int uvi = uv_idx[rid * 64 + m];
            const float4* src =
                (const float4*)(uv_feat + ((long long)(rid >> 13) * 65536 + uvi) * 148);
            for (int f = j - 1; f < 37; f += 3) {
                float4 v = src[f];
                int c0 = 4 * f, c1 = 4 * f + 2;
                act[((c0 >> 3) * 64 + m) * 4 + ((c0 >> 1) & 3)] = split2(v.x, v.y);
                act[((c1 >> 3) * 64 + m) * 4 + ((c1 >> 1) & 3)] = split2(v.z, v.w);
            }
        }
    }
    __syncthreads();

    int ph[2] = {0, 0};
    float acc[4][4][4];

    // ---- layer 1: D1 = X @ W0 (14 chunks) ----
#pragma unroll
    for (int mt = 0; mt < 4; ++mt)
#pragma unroll
        for (int j = 0; j < 4; ++j)
#pragma unroll
            for (int i = 0; i < 4; ++i) acc[mt][j][i] = 0.f;

    for (int c = 0; c < NCH1; ++c) {
        int b = c & 1;
        mbar_wait(mbf[b], ph[b]); ph[b] ^= 1;
        const uint2* wc = (const uint2*)(dsm + OFF_WBUF + b * CHUNK_BYTES);
        do_chunk(act, wc, 2 * c, g, q, wid, acc);
        __syncthreads();
        if (tid == 0 && c + 2 < NCHT) {
            fence_proxy_async();
            issue_chunk(c + 2, wdst[b], mbf[b]);
        }
    }

    // ---- epilogue 1: Act <- split(relu(D1 + b0)) (overwrites union; synced) ----
#pragma unroll
    for (int mt = 0; mt < 4; ++mt)
#pragma unroll
        for (int j = 0; j < 4; ++j) {
            int n = wid * 32 + j * 8 + 2 * q;
            float2 bp = *(const float2*)&b0s[n];
            int m = mt * 16 + g;
            int sidx = wid * 4 + j;
            float h0 = fmaxf(acc[mt][j][0] + bp.x, 0.f);
            float h1 = fmaxf(acc[mt][j][1] + bp.y, 0.f);
            float h2 = fmaxf(acc[mt][j][2] + bp.x, 0.f);
            float h3 = fmaxf(acc[mt][j][3] + bp.y, 0.f);
            act[(sidx * 64 + m) * 4 + q] = split2(h0, h1);
            act[(sidx * 64 + m + 8) * 4 + q] = split2(h2, h3);
        }
    __syncthreads();

    // ---- layer 2: D2 = H1 @ W1 (16 chunks) ----
#pragma unroll
    for (int mt = 0; mt < 4; ++mt)
#pragma unroll
        for (int j = 0; j < 4; ++j)
#pragma unroll
            for (int i = 0; i < 4; ++i) acc[mt][j][i] = 0.f;

    for (int c = NCH1; c < NCHT; ++c) {
        int b = c & 1;
        mbar_wait(mbf[b], ph[b]); ph[b] ^= 1;
        const uint2* wc = (const uint2*)(dsm + OFF_WBUF + b * CHUNK_BYTES);
        do_chunk(act, wc, 2 * (c - NCH1), g, q, wid, acc);
        __syncthreads();
        if (tid == 0 && c + 2 < NCHT) {
            fence_proxy_async();
            issue_chunk(c + 2, wdst[b], mbf[b]);
        }
    }

    // ---- output layer: per-warp partial dots over 32-col slice + quad reduce ----
    {
        float po[8][4];
#pragma unroll
        for (int r8 = 0; r8 < 8; ++r8)
#pragma unroll
            for (int o = 0; o < 4; ++o) po[r8][o] = 0.f;

#pragma unroll
        for (int mt = 0; mt < 4; ++mt)
#pragma unroll
            for (int j = 0; j < 4; ++j) {
                int n = wid * 32 + j * 8 + 2 * q;
                float2 bp = *(const float2*)&b1s[n];
                float4 wa = *(const float4*)&wouts[n * 4];
                float4 wb = *(const float4*)&wouts[(n + 1) * 4];
                float h0 = fmaxf(acc[mt][j][0] + bp.x, 0.f);
                float h1 = fmaxf(acc[mt][j][1] + bp.y, 0.f);
                float h2 = fmaxf(acc[mt][j][2] + bp.x, 0.f);
                float h3 = fmaxf(acc[mt][j][3] + bp.y, 0.f);
                po[mt * 2 + 0][0] += h0 * wa.x + h1 * wb.x;
                po[mt * 2 + 0][1] += h0 * wa.y + h1 * wb.y;
                po[mt * 2 + 0][2] += h0 * wa.z + h1 * wb.z;
                po[mt * 2 + 0][3] += h0 * wa.w + h1 * wb.w;
                po[mt * 2 + 1][0] += h2 * wa.x + h3 * wb.x;
                po[mt * 2 + 1][1] += h2 * wa.y + h3 * wb.y;
                po[mt * 2 + 1][2] += h2 * wa.z + h3 * wb.z;
                po[mt * 2 + 1][3] += h2 * wa.w + h3 * wb.w;
            }
#pragma unroll
        for (int r8 = 0; r8 < 8; ++r8)
#pragma unroll
            for (int o = 0; o < 4; ++o) {
                float v = po[r8][o];
                v += __shfl_xor_sync(0xFFFFFFFFu, v, 1);
                v += __shfl_xor_sync(0xFFFFFFFFu, v, 2);
                po[r8][o] = v;
            }
        if (q == 0) {
#pragma unroll
            for (int r8 = 0; r8 < 8; ++r8) {
                int m = (r8 >> 1) * 16 + g + (r8 & 1) * 8;
#pragma unroll
                for (int o = 0; o < 4; ++o)
                    praw[(m * 4 + o) * 8 + wid] = po[r8][o];
            }
        }
    }
    __syncthreads();

    // ---- shading ----
    if (tid < 64) {
        int m = tid;
        float raw[4];
#pragma unroll
        for (int o = 0; o < 4; ++o) {
            const float* p = &praw[(m * 4 + o) * 8];
            raw[o] = bouts[o] + ((p[0] + p[1]) + (p[2] + p[3]))
                              + ((p[4] + p[5]) + (p[6] + p[7]));
        }
        rgbsm[0 * 64 + m] = 1.f / (1.f + __expf(-raw[0]));
        rgbsm[1 * 64 + m] = 1.f / (1.f + __expf(-raw[1]));
        rgbsm[2 * 64 + m] = 1.f / (1.f + __expf(-raw[2]));
        float sig = fmaxf(raw[3], 0.f);
        float dist = ((m == 63) ? 1e10f : 0.0234375f) * dns[0];
        alphas[m] = 1.f - __expf(-sig * dist);
    }
    __syncthreads();

    // ---- composite ----
    if (tid == 0) {
        float t = 1.f, R = 0.f, G = 0.f, B = 0.f;
#pragma unroll
        for (int s = 0; s < 64; ++s) {
            float a = alphas[s];
            float w = a * t;
            R = fmaf(w, rgbsm[0 * 64 + s], R);
            G = fmaf(w, rgbsm[1 * 64 + s], G);
            B = fmaf(w, rgbsm[2 * 64 + s], B);
            t = t * (1.f - a + 1e-10f);
        }
        out[rid * 3 + 0] = R;
        out[rid * 3 + 1] = G;
        out[rid * 3 + 2] = B;
    }
}

extern "C" void kernel_launch(void* const* d_in, const int* in_sizes, int n_in,
                              void* d_out, int out_size) {
    const float* rays_o     = (const float*)d_in[0];
    const float* rays_d     = (const float*)d_in[1];
    const float* uv_feat    = (const float*)d_in[2];
    const float* transforms = (const float*)d_in[3];
    const float* w0         = (const float*)d_in[4];
    const float* b0         = (const float*)d_in[5];
    const float* w1         = (const float*)d_in[6];
    const float* b1         = (const float*)d_in[7];
    const float* w_out      = (const float*)d_in[8];
    const float* b_out      = (const float*)d_in[9];
    const int*   uv_idx     = (const int*)d_in[10];
    const int*   vox_idx    = (const int*)d_in[11];
    float* out = (float*)d_out;

    vh_prep<<<128, 256>>>(w0, w1);

    cudaFuncSetAttribute(vh_tc, cudaFuncAttributeMaxDynamicSharedMemorySize, DYN_SMEM);
    vh_tc<<<16384, 256, DYN_SMEM>>>(rays_o, rays_d, uv_feat, transforms,
                                    b0, b1, w_out, b_out, uv_idx, vox_idx, out);
}

// round 14
// speedup vs baseline: 3.6822x; 1.2550x over previous
#include <cuda_runtime.h>
#include <cuda_fp16.h>
#include <math.h>
#include <stdint.h>

// ---------------------------------------------------------------------------
// VoxelHuman fused NeRF renderer — split-fp16 (hi+lo) mma.sync m16n8k16 with
// ldmatrix fragment loads. 2 CTAs/SM (M=64, 1 ray per CTA).
//
// smem A storage: two half planes, act_hi / act_lo, each [32 ksteps][64 rows]
// [8 halves] (16B per row-kstep -> ldmatrix-native).
// Weight chunks: [hi: 2 ksteps x 256 n x 8 halves][lo: same] = 16 KB.
// ---------------------------------------------------------------------------

#define NCH1 14                // layer-1 chunks (1 k16 step each; K pad 211->224)
#define NCH2 16                // layer-2 chunks (K = 256)
#define NCHT 30
#define CHUNK_U32 4096         // 16 KB per chunk
#define CHUNK_BYTES 16384

__device__ uint32_t g_wt1[14 * CHUNK_U32];   // split-fp16 W0 (permuted rows)
__device__ uint32_t g_wt2[16 * CHUNK_U32];   // split-fp16 W1

// smem offsets (bytes), per CTA
#define OFF_ACT_HI 0           // 32768
#define OFF_ACT_LO 32768       // 32768
#define OFF_WBUF  65536        // 2 x 16384
#define OFF_PRAW  98304        // 64*4*8 floats = 8192
#define OFF_WOUT  106496       // 1024 floats
#define OFF_B0    110592       // 256 floats
#define OFF_B1    111616       // 256 floats
#define OFF_TS    112640       // 192 floats
#define OFF_BOUT  113408       // 4 floats
#define OFF_DNS   113424       // 1 float
#define OFF_ALPH  113440       // 64 floats
#define OFF_RGB   113696       // 192 floats
#define OFF_MBAR  114464       // 2 x u64
#define DYN_SMEM  114688

__device__ __forceinline__ uint2 split2(float x0, float x1) {
    half2 h = __floats2half2_rn(x0, x1);
    float2 hf = __half22float2(h);
    half2 l = __floats2half2_rn(x0 - hf.x, x1 - hf.y);
    uint2 r;
    r.x = *(uint32_t*)&h;
    r.y = *(uint32_t*)&l;
    return r;
}
__device__ __forceinline__ uint32_t smem_u32(const void* p) {
    return (uint32_t)__cvta_generic_to_shared(p);
}
__device__ __forceinline__ void mbar_init(uint32_t mb, uint32_t cnt) {
    asm volatile("mbarrier.init.shared.b64 [%0], %1;" :: "r"(mb), "r"(cnt) : "memory");
}
__device__ __forceinline__ void mbar_wait(uint32_t mb, int parity) {
    asm volatile(
        "{\n\t.reg .pred P;\n"
        "W_%=:\n\t"
        "mbarrier.try_wait.parity.acquire.cta.shared::cta.b64 P, [%0], %1, 0x989680;\n\t"
        "@!P bra W_%=;\n\t}"
        :: "r"(mb), "r"(parity) : "memory");
}
__device__ __forceinline__ void fence_proxy_async() {
    asm volatile("fence.proxy.async.shared::cta;" ::: "memory");
}
__device__ __forceinline__ void issue_chunk(int c, uint32_t dst, uint32_t mb) {
    const uint32_t* src = (c < NCH1) ? (g_wt1 + c * CHUNK_U32)
                                     : (g_wt2 + (c - NCH1) * CHUNK_U32);
    asm volatile("mbarrier.arrive.expect_tx.shared.b64 _, [%0], %1;"
                 :: "r"(mb), "r"((uint32_t)CHUNK_BYTES) : "memory");
    asm volatile(
        "cp.async.bulk.shared::cluster.global.mbarrier::complete_tx::bytes "
        "[%0], [%1], %2, [%3];"
        :: "r"(dst), "l"(src), "r"((uint32_t)CHUNK_BYTES), "r"(mb) : "memory");
}

__device__ __forceinline__ void ldmx4(uint32_t& r0, uint32_t& r1, uint32_t& r2,
                                      uint32_t& r3, uint32_t a) {
    asm volatile("ldmatrix.sync.aligned.m8n8.x4.shared.b16 {%0,%1,%2,%3}, [%4];"
                 : "=r"(r0), "=r"(r1), "=r"(r2), "=r"(r3) : "r"(a));
}

// m16n8k16 fp16 mma, fp32 accum: D += A*B.
__device__ __forceinline__ void mma16(float d[4], uint32_t a0, uint32_t a1,
                                      uint32_t a2, uint32_t a3,
                                      uint32_t b0, uint32_t b1) {
    asm volatile(
        "mma.sync.aligned.m16n8k16.row.col.f32.f16.f16.f32 "
        "{%0,%1,%2,%3}, {%4,%5,%6,%7}, {%8,%9}, {%0,%1,%2,%3};"
        : "+f"(d[0]), "+f"(d[1]), "+f"(d[2]), "+f"(d[3])
        : "r"(a0), "r"(a1), "r"(a2), "r"(a3), "r"(b0), "r"(b1));
}

// Accurate sincos (immune to --use_fast_math): fp32 Cody-Waite + MUFU.
__device__ __forceinline__ void sincos_acc(float x, float& s, float& c) {
    float q = rintf(x * 0.63661977236758134f);
    float r = fmaf(q, -1.5707962513e+00f, x);
    r = fmaf(q, -7.5497894159e-08f, r);
    int qi = (int)q & 3;
    float sr = __sinf(r), cr = __cosf(r);
    float ss = (qi & 1) ? cr : sr;
    float cc = (qi & 1) ? sr : cr;
    s = (qi & 2) ? -ss : ss;
    c = ((qi + 1) & 2) ? -cc : cc;
}

// ---------------------------------------------------------------------------
// Prep: transpose + fp16-split weights into ldmatrix-native chunk layout.
// u32 index i: c = i>>11? no: per chunk 4096 u32. i: c = i>>12? CHUNK_U32=4096.
//   c = i / 4096 handled via launch split below. Within logical (c,t,n,h2):
//   hi word at c*4096 + (t*256+n)*4 + h2 ; lo at +2048. k0 = (2c+t)*8 + 2*h2.
// Layer-1 K-col -> W0 row permutation: col<148 -> 63+col (features);
// col in [148,211) -> col-148 (embedding); col>=211 -> zero pad.
// ---------------------------------------------------------------------------
__global__ void vh_prep(const float* __restrict__ w0, const float* __restrict__ w1) {
    int i = blockIdx.x * 256 + threadIdx.x;   // 65536 threads = (c,t,n,h2) ids
    int c = i >> 11;                          // 2048 ids per chunk (hi+lo pair)
    int rem = i & 2047;                       // (t,n,h2)
    int t = rem >> 10, n = (rem >> 2) & 255, h2 = rem & 3;
    int k0 = (2 * c + t) * 8 + 2 * h2, k1 = k0 + 1;
    int hi_idx = c * CHUNK_U32 + (t * 256 + n) * 4 + h2;
    if (c < 14) {
        int r0 = (k0 < 148) ? 63 + k0 : ((k0 < 211) ? k0 - 148 : -1);
        int r1 = (k1 < 148) ? 63 + k1 : ((k1 < 211) ? k1 - 148 : -1);
        float v0 = (r0 >= 0) ? w0[r0 * 256 + n] : 0.f;
        float v1 = (r1 >= 0) ? w0[r1 * 256 + n] : 0.f;
        uint2 u = split2(v0, v1);
        g_wt1[hi_idx] = u.x;
        g_wt1[hi_idx + 2048] = u.y;
    }
    if (c < 16) {
        uint2 u = split2(w1[k0 * 256 + n], w1[k1 * 256 + n]);
        g_wt2[hi_idx] = u.x;
        g_wt2[hi_idx + 2048] = u.y;
    }
}

// one chunk = one k16 step. Warp w owns cols [32w, 32w+32). 12 LDSM + 48 mma.
__device__ __forceinline__ void do_chunk(uint32_t aHi, uint32_t aLo, uint32_t bA,
                                         float acc[4][4][4]) {
    uint32_t b0h[4], b1h[4], b0l[4], b1l[4];
    ldmx4(b0h[0], b0h[1], b0h[2], b0h[3], bA);
    ldmx4(b1h[0], b1h[1], b1h[2], b1h[3], bA + 4096);
    ldmx4(b0l[0], b0l[1], b0l[2], b0l[3], bA + 8192);
    ldmx4(b1l[0], b1l[1], b1l[2], b1l[3], bA + 12288);
#pragma unroll
    for (int mt = 0; mt < 4; ++mt) {
        uint32_t ah0, ah1, ah2, ah3, al0, al1, al2, al3;
        ldmx4(ah0, ah1, ah2, ah3, aHi + mt * 256);
        ldmx4(al0, al1, al2, al3, aLo + mt * 256);
#pragma unroll
        for (int j = 0; j < 4; ++j) {
            mma16(acc[mt][j], ah0, ah1, ah2, ah3, b0h[j], b1h[j]);   // hi*hi
            mma16(acc[mt][j], ah0, ah1, ah2, ah3, b0l[j], b1l[j]);   // hi*lo
            mma16(acc[mt][j], al0, al1, al2, al3, b0h[j], b1h[j]);   // lo*hi
        }
    }
}

__global__ __launch_bounds__(256, 2)
void vh_tc(const float* __restrict__ rays_o, const float* __restrict__ rays_d,
           const float* __restrict__ uv_feat, const float* __restrict__ transforms,
           const float* __restrict__ b0, const float* __restrict__ b1,
           const float* __restrict__ w_out, const float* __restrict__ b_out,
           const int* __restrict__ uv_idx, const int* __restrict__ vox_idx,
           float* __restrict__ out) {
    extern __shared__ char dsm[];
    const int tid = threadIdx.x;
    const int wid = tid >> 5, lane = tid & 31;
    const int g = lane >> 2, q = lane & 3;
    const int rid = blockIdx.x;                  // 1 ray per CTA

    uint32_t* actHi = (uint32_t*)(dsm + OFF_ACT_HI);
    uint32_t* actLo = (uint32_t*)(dsm + OFF_ACT_LO);
    float* praw  = (float*)(dsm + OFF_PRAW);
    float* wouts = (float*)(dsm + OFF_WOUT);
    float* b0s   = (float*)(dsm + OFF_B0);
    float* b1s   = (float*)(dsm + OFF_B1);
    float* Ts    = (float*)(dsm + OFF_TS);
    float* bouts = (float*)(dsm + OFF_BOUT);
    float* dns   = (float*)(dsm + OFF_DNS);
    float* alphas = (float*)(dsm + OFF_ALPH);
    float* rgbsm  = (float*)(dsm + OFF_RGB);
    uint32_t mbf[2] = {smem_u32(dsm + OFF_MBAR), smem_u32(dsm + OFF_MBAR + 8)};
    uint32_t wdst[2] = {smem_u32(dsm + OFF_WBUF), smem_u32(dsm + OFF_WBUF + CHUNK_BYTES)};

    // kick off weight streaming immediately (overlaps with build phase)
    if (tid == 0) {
        mbar_init(mbf[0], 1);
        mbar_init(mbf[1], 1);
        fence_proxy_async();
        issue_chunk(0, wdst[0], mbf[0]);
        issue_chunk(1, wdst[1], mbf[1]);
    }

    // stage constants
    if (tid < 192) Ts[tid] = transforms[tid];
    b0s[tid] = b0[tid];
    b1s[tid] = b1[tid];
    for (int i = tid; i < 1024; i += 256) wouts[i] = w_out[i];
    if (tid < 4) bouts[tid] = b_out[tid];
    __syncthreads();

    // ---- build X [64 rows][224 cols] into hi/lo planes (4 threads / row) ----
    // u32 slot for (kstep s, row m, half-pair h2): (s*64 + m)*4 + h2
    {
        const int m = tid >> 2, j = tid & 3;   // m = sample
        if (j == 0) {
            // embedding -> cols 148..210, pad 211..223
            float ro0 = rays_o[rid * 3], ro1 = rays_o[rid * 3 + 1], ro2 = rays_o[rid * 3 + 2];
            float rd0 = rays_d[rid * 3], rd1 = rays_d[rid * 3 + 1], rd2 = rays_d[rid * 3 + 2];
            if (m == 0)
                dns[0] = sqrtf(rd0 * rd0 + rd1 * rd1 + rd2 * rd2);
            int vox = vox_idx[rid * 64 + m];
            float z = 0.5f + 0.0234375f * (float)m;
            float px = fmaf(rd0, z, ro0), py = fmaf(rd1, z, ro1), pz = fmaf(rd2, z, ro2);
            const float* T = &Ts[vox * 12];
            float cx = T[0] * px + T[1] * py + T[2]  * pz + T[3];
            float cy = T[4] * px + T[5] * py + T[6]  * pz + T[7];
            float cz = T[8] * px + T[9] * py + T[10] * pz + T[11];
            float e[64];
            e[0] = cx; e[1] = cy; e[2] = cz; e[63] = 0.f;
#pragma unroll
            for (int kf = 0; kf < 10; ++kf) {
                float f = (float)(1 << kf);
                float sx, cxs, sy, cys, sz, czs;
                sincos_acc(f * cx, sx, cxs);
                sincos_acc(f * cy, sy, cys);
                sincos_acc(f * cz, sz, czs);
                int r = 3 + 6 * kf;
                e[r + 0] = sx; e[r + 1] = sy; e[r + 2] = sz;
                e[r + 3] = cxs; e[r + 4] = cys; e[r + 5] = czs;
            }
#pragma unroll
            for (int pe = 0; pe < 32; ++pe) {
                int c = 148 + 2 * pe;
                int idx = ((c >> 3) * 64 + m) * 4 + ((c & 7) >> 1);
                uint2 u = split2(e[2 * pe], e[2 * pe + 1]);
                actHi[idx] = u.x;
                actLo[idx] = u.y;
            }
#pragma unroll
            for (int pc = 0; pc < 6; ++pc) {
                int c = 212 + 2 * pc;
                int idx = ((c >> 3) * 64 + m) * 4 + ((c & 7) >> 1);
                actHi[idx] = 0u;
                actLo[idx] = 0u;
            }
        } else {
            // features -> cols 0..147 (j=1,2,3 split the 37 float4s)
            int uvi = uv_idx[rid * 64 + m];
            const float4* src =
                (const float4*)(uv_feat + ((long long)(rid >> 13) * 65536 + uvi) * 148);
            for (int f = j - 1; f < 37; f += 3) {
                float4 v = src[f];
                int idx = ((f >> 1) * 64 + m) * 4 + (f & 1) * 2;
                uint2 u0 = split2(v.x, v.y);
                uint2 u1 = split2(v.z, v.w);
                actHi[idx] = u0.x;     actLo[idx] = u0.y;
                actHi[idx + 1] = u1.x; actLo[idx + 1] = u1.y;
            }
        }
    }
    __syncthreads();

    // lane-invariant fragment addresses
    const uint32_t aoffA = ((lane >> 4) * 64 + (lane & 7) + ((lane >> 3) & 1) * 8) * 16;
    const uint32_t aHiB = smem_u32(dsm + OFF_ACT_HI) + aoffA;
    const uint32_t aLoB = smem_u32(dsm + OFF_ACT_LO) + aoffA;
    const uint32_t boff = (wid * 32 + (lane >> 3) * 8 + (lane & 7)) * 16;

    int ph[2] = {0, 0};
    float acc[4][4][4];

    // ---- layer 1: D1 = X @ W0 (14 chunks) ----
#pragma unroll
    for (int mt = 0; mt < 4; ++mt)
#pragma unroll
        for (int j = 0; j < 4; ++j)
#pragma unroll
            for (int i = 0; i < 4; ++i) acc[mt][j][i] = 0.f;

    for (int c = 0; c < NCH1; ++c) {
        int b = c & 1;
        mbar_wait(mbf[b], ph[b]); ph[b] ^= 1;
        do_chunk(aHiB + c * 2048, aLoB + c * 2048, wdst[b] + boff, acc);
        __syncthreads();
        if (tid == 0 && c + 2 < NCHT) {
            fence_proxy_async();
            issue_chunk(c + 2, wdst[b], mbf[b]);
        }
    }

    // ---- epilogue 1: Act <- split(relu(D1 + b0)) (overwrites union; synced) ----
#pragma unroll
    for (int mt = 0; mt < 4; ++mt)
#pragma unroll
        for (int j = 0; j < 4; ++j) {
            int n = wid * 32 + j * 8 + 2 * q;
            float2 bp = *(const float2*)&b0s[n];
            int m = mt * 16 + g;
            int sidx = wid * 4 + j;
            float h0 = fmaxf(acc[mt][j][0] + bp.x, 0.f);
            float h1 = fmaxf(acc[mt][j][1] + bp.y, 0.f);
            float h2 = fmaxf(acc[mt][j][2] + bp.x, 0.f);
            float h3 = fmaxf(acc[mt][j][3] + bp.y, 0.f);
            uint2 u01 = split2(h0, h1);
            uint2 u23 = split2(h2, h3);
            actHi[(sidx * 64 + m) * 4 + q] = u01.x;
            actLo[(sidx * 64 + m) * 4 + q] = u01.y;
            actHi[(sidx * 64 + m + 8) * 4 + q] = u23.x;
            actLo[(sidx * 64 + m + 8) * 4 + q] = u23.y;
        }
    __syncthreads();

    // ---- layer 2: D2 = H1 @ W1 (16 chunks) ----
#pragma unroll
    for (int mt = 0; mt < 4; ++mt)
#pragma unroll
        for (int j = 0; j < 4; ++j)
#pragma unroll
            for (int i = 0; i < 4; ++i) acc[mt][j][i] = 0.f;

    for (int c = NCH1; c < NCHT; ++c) {
        int b = c & 1;
        mbar_wait(mbf[b], ph[b]); ph[b] ^= 1;
        int s2 = c - NCH1;
        do_chunk(aHiB + s2 * 2048, aLoB + s2 * 2048, wdst[b] + boff, acc);
        __syncthreads();
        if (tid == 0 && c + 2 < NCHT) {
            fence_proxy_async();
            issue_chunk(c + 2, wdst[b], mbf[b]);
        }
    }

    // ---- output layer: per-warp partial dots over 32-col slice + quad reduce ----
    {
        float po[8][4];
#pragma unroll
        for (int r8 = 0; r8 < 8; ++r8)
#pragma unroll
            for (int o = 0; o < 4; ++o) po[r8][o] = 0.f;

#pragma unroll
        for (int mt = 0; mt < 4; ++mt)
#pragma unroll
            for (int j = 0; j < 4; ++j) {
                int n = wid * 32 + j * 8 + 2 * q;
                float2 bp = *(const float2*)&b1s[n];
                float4 wa = *(const float4*)&wouts[n * 4];
                float4 wb = *(const float4*)&wouts[(n + 1) * 4];
                float h0 = fmaxf(acc[mt][j][0] + bp.x, 0.f);
                float h1 = fmaxf(acc[mt][j][1] + bp.y, 0.f);
                float h2 = fmaxf(acc[mt][j][2] + bp.x, 0.f);
                float h3 = fmaxf(acc[mt][j][3] + bp.y, 0.f);
                po[mt * 2 + 0][0] += h0 * wa.x + h1 * wb.x;
                po[mt * 2 + 0][1] += h0 * wa.y + h1 * wb.y;
                po[mt * 2 + 0][2] += h0 * wa.z + h1 * wb.z;
                po[mt * 2 + 0][3] += h0 * wa.w + h1 * wb.w;
                po[mt * 2 + 1][0] += h2 * wa.x + h3 * wb.x;
                po[mt * 2 + 1][1] += h2 * wa.y + h3 * wb.y;
                po[mt * 2 + 1][2] += h2 * wa.z + h3 * wb.z;
                po[mt * 2 + 1][3] += h2 * wa.w + h3 * wb.w;
            }
#pragma unroll
        for (int r8 = 0; r8 < 8; ++r8)
#pragma unroll
            for (int o = 0; o < 4; ++o) {
                float v = po[r8][o];
                v += __shfl_xor_sync(0xFFFFFFFFu, v, 1);
                v += __shfl_xor_sync(0xFFFFFFFFu, v, 2);
                po[r8][o] = v;
            }
        if (q == 0) {
#pragma unroll
            for (int r8 = 0; r8 < 8; ++r8) {
                int m = (r8 >> 1) * 16 + g + (r8 & 1) * 8;
#pragma unroll
                for (int o = 0; o < 4; ++o)
                    praw[(m * 4 + o) * 8 + wid] = po[r8][o];
            }
        }
    }
    __syncthreads();

    // ---- shading ----
    if (tid < 64) {
        int m = tid;
        float raw[4];
#pragma unroll
        for (int o = 0; o < 4; ++o) {
            const float* p = &praw[(m * 4 + o) * 8];
            raw[o] = bouts[o] + ((p[0] + p[1]) + (p[2] + p[3]))
                              + ((p[4] + p[5]) + (p[6] + p[7]));
        }
        rgbsm[0 * 64 + m] = 1.f / (1.f + __expf(-raw[0]));
        rgbsm[1 * 64 + m] = 1.f / (1.f + __expf(-raw[1]));
        rgbsm[2 * 64 + m] = 1.f / (1.f + __expf(-raw[2]));
        float sig = fmaxf(raw[3], 0.f);
        float dist = ((m == 63) ? 1e10f : 0.0234375f) * dns[0];
        alphas[m] = 1.f - __expf(-sig * dist);
    }
    __syncthreads();

    // ---- composite ----
    if (tid == 0) {
        float t = 1.f, R = 0.f, G = 0.f, B = 0.f;
#pragma unroll
        for (int s = 0; s < 64; ++s) {
            float a = alphas[s];
            float w = a * t;
            R = fmaf(w, rgbsm[0 * 64 + s], R);
            G = fmaf(w, rgbsm[1 * 64 + s], G);
            B = fmaf(w, rgbsm[2 * 64 + s], B);
            t = t * (1.f - a + 1e-10f);
        }
        out[rid * 3 + 0] = R;
        out[rid * 3 + 1] = G;
        out[rid * 3 + 2] = B;
    }
}

extern "C" void kernel_launch(void* const* d_in, const int* in_sizes, int n_in,
                              void* d_out, int out_size) {
    const float* rays_o     = (const float*)d_in[0];
    const float* rays_d     = (const float*)d_in[1];
    const float* uv_feat    = (const float*)d_in[2];
    const float* transforms = (const float*)d_in[3];
    const float* w0         = (const float*)d_in[4];
    const float* b0         = (const float*)d_in[5];
    const float* w1         = (const float*)d_in[6];
    const float* b1         = (const float*)d_in[7];
    const float* w_out      = (const float*)d_in[8];
    const float* b_out      = (const float*)d_in[9];
    const int*   uv_idx     = (const int*)d_in[10];
    const int*   vox_idx    = (const int*)d_in[11];
    float* out = (float*)d_out;

    vh_prep<<<128, 256>>>(w0, w1);

    cudaFuncSetAttribute(vh_tc, cudaFuncAttributeMaxDynamicSharedMemorySize, DYN_SMEM);
    vh_tc<<<16384, 256, DYN_SMEM>>>(rays_o, rays_d, uv_feat, transforms,
                                    b0, b1, w_out, b_out, uv_idx, vox_idx, out);
}